// round 2
// baseline (speedup 1.0000x reference)
#include <cuda_runtime.h>

// ---------------------------------------------------------------------------
// CGCNN: B=16, N=1024, M=12, F=64, BF=128, N_CONV=3, VOCAB=100
// Decomposition: total@W = x@W1 + gather(x@W2) + bond@W3
// ---------------------------------------------------------------------------

#define BN_ALPHA 0.99950037f   // 1/sqrt(1+1e-3) in fp32

// scratch (device globals are the allowed scratch mechanism)
__device__ float g_X0[16 * 1024 * 64];
__device__ float g_X1[16 * 1024 * 64];
__device__ float g_Y1[16 * 1024 * 64];
__device__ float g_Y2[16 * 1024 * 64];
__device__ float g_S1[16 * 1024];
__device__ float g_S2[16 * 1024];

// ---- f32x2 packed FMA helpers (Blackwell FFMA2) ---------------------------
__device__ __forceinline__ unsigned long long pk2(float x, float y) {
    unsigned long long r;
    asm("mov.b64 %0, {%1, %2};" : "=l"(r)
        : "r"(__float_as_uint(x)), "r"(__float_as_uint(y)));
    return r;
}
__device__ __forceinline__ void fma2(unsigned long long& d,
                                     unsigned long long a,
                                     unsigned long long b) {
    asm("fma.rn.f32x2 %0, %1, %2, %0;" : "+l"(d) : "l"(a), "l"(b));
}
__device__ __forceinline__ float2 up2(unsigned long long v) {
    unsigned lo, hi;
    asm("mov.b64 {%0, %1}, %2;" : "=r"(lo), "=r"(hi) : "l"(v));
    float2 r;
    r.x = __uint_as_float(lo);
    r.y = __uint_as_float(hi);
    return r;
}
__device__ __forceinline__ void cp16(unsigned smem, const void* g) {
    asm volatile("cp.async.cg.shared.global [%0], [%1], 16;" ::"r"(smem), "l"(g));
}

// ---------------------------------------------------------------------------
// Embedding gather: X0[b,n,:] = emb[atom_types[b,n],:]
// grid 1024 x 256 : one float4 per thread
// ---------------------------------------------------------------------------
__global__ void embed_k(const int* __restrict__ types,
                        const float* __restrict__ emb) {
    int q = blockIdx.x * 256 + threadIdx.x;   // < 262144
    int node = q >> 4;
    int j = q & 15;
    int t = types[node];
    float4 v = *(const float4*)(emb + t * 64 + j * 4);
    *(float4*)(g_X0 + node * 64 + j * 4) = v;
}

// ---------------------------------------------------------------------------
// Projections: Y1 = x@cw1, Y2 = x@cw2, S1 = x@fw1, S2 = x@fw2
// grid 256 blocks, 64 rows each, 256 threads, 4x8 micro-tiles, FFMA2
// dyn smem: xs[64*68] + ws[64*130]
// ---------------------------------------------------------------------------
#define PROJ_SMEM ((64 * 68 + 64 * 130) * 4)

__global__ void __launch_bounds__(256) proj_k(int flip,
                                              const float* __restrict__ cw12,
                                              const float* __restrict__ fw12) {
    extern __shared__ float sm[];
    float* xs = sm;              // 64 x 68 (padded)
    float* ws = sm + 64 * 68;    // 64 x 130 : [cw1 | cw2 | fw1 | fw2]
    const float* Xc = flip ? g_X1 : g_X0;

    int tid = threadIdx.x;
    int row0 = blockIdx.x * 64;

    for (int t = tid; t < 1024; t += 256) {
        int r = t >> 4, q = t & 15;
        float4 v = *(const float4*)(Xc + (row0 + r) * 64 + q * 4);
        *(float4*)(xs + r * 68 + q * 4) = v;
    }
    for (int t = tid; t < 64 * 128; t += 256) {
        int k = t >> 7, c = t & 127;
        ws[k * 130 + c] = cw12[(c < 64 ? k : 64 + k) * 64 + (c & 63)];
    }
    if (tid < 64) {
        ws[tid * 130 + 128] = fw12[tid];
        ws[tid * 130 + 129] = fw12[64 + tid];
    }
    __syncthreads();

    int rg = tid & 15, cg = tid >> 4;   // 16 row-groups x 16 col-groups
    unsigned long long acc[4][4];
#pragma unroll
    for (int i = 0; i < 4; i++)
#pragma unroll
        for (int p = 0; p < 4; p++) acc[i][p] = 0ull;

#pragma unroll 1
    for (int k = 0; k < 64; k += 4) {
        float4 a[4];
#pragma unroll
        for (int i = 0; i < 4; i++)
            a[i] = *(const float4*)(xs + (rg + 16 * i) * 68 + k);
#pragma unroll
        for (int j = 0; j < 4; j++) {
            unsigned long long bv[4];
#pragma unroll
            for (int p = 0; p < 4; p++)
                bv[p] = *(const unsigned long long*)(ws + (k + j) * 130 +
                                                     cg * 8 + 2 * p);
#pragma unroll
            for (int i = 0; i < 4; i++) {
                float av = ((const float*)(a + i))[j];
                unsigned long long aa = pk2(av, av);
#pragma unroll
                for (int p = 0; p < 4; p++) fma2(acc[i][p], aa, bv[p]);
            }
        }
    }

#pragma unroll
    for (int i = 0; i < 4; i++) {
        int grow = row0 + rg + 16 * i;
#pragma unroll
        for (int p = 0; p < 4; p++) {
            int c = cg * 8 + 2 * p;
            float2 v = up2(acc[i][p]);
            if (c < 64)
                *(float2*)(g_Y1 + grow * 64 + c) = v;
            else
                *(float2*)(g_Y2 + grow * 64 + (c - 64)) = v;
        }
    }

    if (tid < 64) {
        int grow = row0 + tid;
        float s1 = 0.f, s2 = 0.f;
        for (int k = 0; k < 64; k++) {
            float xv = xs[tid * 68 + k];
            s1 += xv * ws[k * 130 + 128];
            s2 += xv * ws[k * 130 + 129];
        }
        g_S1[grow] = s1;
        g_S2[grow] = s2;
    }
}

// ---------------------------------------------------------------------------
// Main conv: one block = 16 atoms (192 (n,m) rows).
//   GEMM: C[192][64] = bond[192][128] @ cw3[128][64]   (FFMA2, 6x8 tiles)
//   Epilogue: +y1 +y2[nbr] +cb, BN, relu, softmax(filt) over m, weighted
//             mean, BN, residual relu -> X_next
// grid 1024, 256 threads, dyn smem ~134KB (1 block/SM)
// ---------------------------------------------------------------------------
#define CONV_SMEM ((25344 + 8448 + 128 + 192) * 4 + 192 * 4)

__global__ void __launch_bounds__(256, 1)
conv_k(int flip, const float* __restrict__ bond, const int* __restrict__ nbrl,
       const float* __restrict__ cw3, const float* __restrict__ fw3,
       const float* __restrict__ cb, const float* __restrict__ fb,
       const float* __restrict__ bag, const float* __restrict__ bab,
       const float* __restrict__ bbg, const float* __restrict__ bbb) {
    extern __shared__ float sm[];
    float* bs = sm;                    // 192 x 132 (padded) bond tile
    float* ws = sm + 25344;            // 128 x 66 weights (k-major, c contig)
    float* fs = ws + 8448;             // 128 filter weights
    float* ft = fs + 128;              // 192 filter values / softmax weights
    int* nb = (int*)(ft + 192);        // 192 neighbor ids

    const float* Xc = flip ? g_X1 : g_X0;
    float* Xn = flip ? g_X0 : g_X1;

    int tid = threadIdx.x;
    int b = blockIdx.x >> 6;
    int n0 = (blockIdx.x & 63) << 4;
    int bn0 = b * 1024 + n0;
    const float* gb = bond + (size_t)bn0 * 12 * 128;

    unsigned bs_s = (unsigned)__cvta_generic_to_shared(bs);
    // two-stage async load of the 96KB bond tile (k halves)
    for (int h = 0; h < 2; h++) {
        for (int t = tid; t < 3072; t += 256) {
            int r = t >> 4, q = t & 15;
            int k = h * 64 + q * 4;
            cp16(bs_s + (r * 132 + k) * 4, gb + r * 128 + k);
        }
        asm volatile("cp.async.commit_group;");
    }
    // weights (small, regular loads)
    for (int t = tid; t < 8192; t += 256) {
        int k = t >> 6, c = t & 63;
        ws[k * 66 + c] = cw3[k * 64 + c];
    }
    if (tid < 128) fs[tid] = fw3[tid];

    int lane = tid & 31, w = tid >> 5;
    int wc = w * 8;   // warp = column group -> B loads broadcast
    unsigned long long acc[6][4];
#pragma unroll
    for (int i = 0; i < 6; i++)
#pragma unroll
        for (int p = 0; p < 4; p++) acc[i][p] = 0ull;

    for (int half = 0; half < 2; half++) {
        if (half == 0)
            asm volatile("cp.async.wait_group 1;");
        else
            asm volatile("cp.async.wait_group 0;");
        __syncthreads();
        int kb = half * 64;
#pragma unroll 1
        for (int kk = 0; kk < 64; kk += 4) {
            int k0 = kb + kk;
            float4 a[6];
#pragma unroll
            for (int i = 0; i < 6; i++)
                a[i] = *(const float4*)(bs + (lane + 32 * i) * 132 + k0);
#pragma unroll
            for (int j = 0; j < 4; j++) {
                unsigned long long bv[4];
#pragma unroll
                for (int p = 0; p < 4; p++)
                    bv[p] = *(const unsigned long long*)(ws + (k0 + j) * 66 +
                                                         wc + 2 * p);
#pragma unroll
                for (int i = 0; i < 6; i++) {
                    float av = ((const float*)(a + i))[j];
                    unsigned long long aa = pk2(av, av);
#pragma unroll
                    for (int p = 0; p < 4; p++) fma2(acc[i][p], aa, bv[p]);
                }
            }
        }
    }

    // filter logits (needs bond tile still in smem)
    float fbv = fb[0];
    if (tid < 192) {
        int row = tid;
        int a_ = row / 12, m = row - a_ * 12;
        int nglob = bn0 + a_;
        int nbr = nbrl[nglob * 12 + m];
        nb[row] = nbr;
        float acc2 = 0.f;
#pragma unroll 8
        for (int k = 0; k < 128; k += 4) {
            float4 bvv = *(const float4*)(bs + row * 132 + k);
            float4 fv = *(const float4*)(fs + k);
            acc2 += bvv.x * fv.x + bvv.y * fv.y + bvv.z * fv.z + bvv.w * fv.w;
        }
        ft[row] = acc2 + g_S1[nglob] + g_S2[b * 1024 + nbr] + fbv;
    }
    __syncthreads();

    // softmax over m (folding the 1/12 mean), done by 16 threads
    if (tid < 16) {
        int base = tid * 12;
        float mx = -1e30f;
#pragma unroll
        for (int m = 0; m < 12; m++) mx = fmaxf(mx, ft[base + m]);
        float s = 0.f;
#pragma unroll
        for (int m = 0; m < 12; m++) s += expf(ft[base + m] - mx);
        float inv = 1.f / (12.f * s);
#pragma unroll
        for (int m = 0; m < 12; m++) ft[base + m] = expf(ft[base + m] - mx) * inv;
    }

    // core epilogue: C + y1 + y2[nbr] + cb -> BN -> relu -> Cs (reuses bs)
    float* Cs = bs;   // 192 x 65
#pragma unroll
    for (int i = 0; i < 6; i++) {
        int row = lane + 32 * i;
        int a_ = row / 12;
        int nglob = bn0 + a_;
        int nbr = nb[row];
        const float* y1p = g_Y1 + nglob * 64 + wc;
        const float* y2p = g_Y2 + (b * 1024 + nbr) * 64 + wc;
#pragma unroll
        for (int p = 0; p < 4; p++) {
            int c = wc + 2 * p;
            float2 v = up2(acc[i][p]);
            float v0 = v.x + y1p[2 * p] + y2p[2 * p] + __ldg(cb + c);
            float v1 = v.y + y1p[2 * p + 1] + y2p[2 * p + 1] + __ldg(cb + c + 1);
            v0 = fmaxf(__ldg(bag + c) * (v0 * BN_ALPHA) + __ldg(bab + c), 0.f);
            v1 = fmaxf(__ldg(bag + c + 1) * (v1 * BN_ALPHA) + __ldg(bab + c + 1),
                       0.f);
            Cs[row * 65 + c] = v0;
            Cs[row * 65 + c + 1] = v1;
        }
    }
    __syncthreads();

    // weighted mean over m, BN, residual relu
#pragma unroll
    for (int q = 0; q < 4; q++) {
        int idx = tid + 256 * q;   // < 1024
        int a_ = idx >> 6, c = idx & 63;
        float s = 0.f;
#pragma unroll
        for (int m = 0; m < 12; m++)
            s += ft[a_ * 12 + m] * Cs[(a_ * 12 + m) * 65 + c];
        s = __ldg(bbg + c) * (s * BN_ALPHA) + __ldg(bbb + c);
        int gi = (bn0 + a_) * 64 + c;
        Xn[gi] = fmaxf(Xc[gi] + s, 0.f);
    }
}

// ---------------------------------------------------------------------------
// Final: crys = relu(gather(x, target_index)); out = relu(crys@dense_w + db)
// grid 16 (per batch), 256 threads
// ---------------------------------------------------------------------------
__global__ void __launch_bounds__(256) final_k(const int* __restrict__ tix,
                                               const float* __restrict__ dw,
                                               const float* __restrict__ db,
                                               float* __restrict__ out) {
    __shared__ float cs[64 * 68];
    __shared__ float wd[64 * 65];
    int b = blockIdx.x, tid = threadIdx.x;
    for (int t = tid; t < 4096; t += 256) {
        int k = t >> 6, f = t & 63;
        wd[k * 65 + f] = dw[t];
    }
    for (int t = tid; t < 1024; t += 256) {
        int j = t >> 4, q = t & 15;
        int ti = tix[b * 64 + j];
        float4 v = *(const float4*)(g_X1 + (b * 1024 + ti) * 64 + q * 4);
        v.x = fmaxf(v.x, 0.f);
        v.y = fmaxf(v.y, 0.f);
        v.z = fmaxf(v.z, 0.f);
        v.w = fmaxf(v.w, 0.f);
        *(float4*)(cs + j * 68 + q * 4) = v;
    }
    __syncthreads();
    for (int t = tid; t < 4096; t += 256) {
        int j = t >> 6, f = t & 63;
        float acc = db[f];
#pragma unroll 8
        for (int k = 0; k < 64; k++) acc += cs[j * 68 + k] * wd[k * 65 + f];
        out[b * 4096 + t] = fmaxf(acc, 0.f);
    }
}

// ---------------------------------------------------------------------------
extern "C" void kernel_launch(void* const* d_in, const int* in_sizes, int n_in,
                              void* d_out, int out_size) {
    const int* atom_types = (const int*)d_in[0];
    const float* bond = (const float*)d_in[1];
    const int* nbrl = (const int*)d_in[2];
    const int* tix = (const int*)d_in[3];
    const float* emb = (const float*)d_in[4];
    const float* core_w = (const float*)d_in[5];
    const float* core_b = (const float*)d_in[6];
    const float* filt_w = (const float*)d_in[7];
    const float* filt_b = (const float*)d_in[8];
    const float* bna_g = (const float*)d_in[9];
    const float* bna_b = (const float*)d_in[10];
    const float* bnb_g = (const float*)d_in[11];
    const float* bnb_b = (const float*)d_in[12];
    const float* dw = (const float*)d_in[13];
    const float* db = (const float*)d_in[14];
    float* out = (float*)d_out;

    cudaFuncSetAttribute(proj_k, cudaFuncAttributeMaxDynamicSharedMemorySize,
                         PROJ_SMEM);
    cudaFuncSetAttribute(conv_k, cudaFuncAttributeMaxDynamicSharedMemorySize,
                         CONV_SMEM);

    embed_k<<<1024, 256>>>(atom_types, emb);
    for (int l = 0; l < 3; l++) {
        int flip = l & 1;
        proj_k<<<256, 256, PROJ_SMEM>>>(flip, core_w + l * 256 * 64,
                                        filt_w + l * 256);
        conv_k<<<1024, 256, CONV_SMEM>>>(
            flip, bond, nbrl, core_w + l * 256 * 64 + 128 * 64,
            filt_w + l * 256 + 128, core_b + l * 64, filt_b + l,
            bna_g + l * 64, bna_b + l * 64, bnb_g + l * 64, bnb_b + l * 64);
    }
    final_k<<<16, 256>>>(tix, dw, db, out);
}

// round 3
// speedup vs baseline: 1.0028x; 1.0028x over previous
#include <cuda_runtime.h>

// ---------------------------------------------------------------------------
// CGCNN: B=16, N=1024, M=12, F=64, BF=128, N_CONV=3, VOCAB=100
// Decomposition: total@W = x@W1 + gather(x@W2) + bond@W3
// ---------------------------------------------------------------------------

#define BN_ALPHA 0.99950037f   // 1/sqrt(1+1e-3) in fp32

// scratch (device globals are the allowed scratch mechanism)
__device__ float g_X0[16 * 1024 * 64];
__device__ float g_X1[16 * 1024 * 64];
__device__ float g_Y1[16 * 1024 * 64];
__device__ float g_Y2[16 * 1024 * 64];
__device__ float g_S1[16 * 1024];
__device__ float g_S2[16 * 1024];

// ---- f32x2 packed FMA helpers (Blackwell FFMA2) ---------------------------
__device__ __forceinline__ unsigned long long pk2(float x, float y) {
    unsigned long long r;
    asm("mov.b64 %0, {%1, %2};" : "=l"(r)
        : "r"(__float_as_uint(x)), "r"(__float_as_uint(y)));
    return r;
}
__device__ __forceinline__ void fma2(unsigned long long& d,
                                     unsigned long long a,
                                     unsigned long long b) {
    asm("fma.rn.f32x2 %0, %1, %2, %0;" : "+l"(d) : "l"(a), "l"(b));
}
__device__ __forceinline__ float2 up2(unsigned long long v) {
    unsigned lo, hi;
    asm("mov.b64 {%0, %1}, %2;" : "=r"(lo), "=r"(hi) : "l"(v));
    float2 r;
    r.x = __uint_as_float(lo);
    r.y = __uint_as_float(hi);
    return r;
}
__device__ __forceinline__ void cp16(unsigned smem, const void* g) {
    asm volatile("cp.async.cg.shared.global [%0], [%1], 16;" ::"r"(smem), "l"(g));
}

// ---------------------------------------------------------------------------
// Embedding gather: X0[b,n,:] = emb[atom_types[b,n],:]
// grid 1024 x 256 : one float4 per thread
// ---------------------------------------------------------------------------
__global__ void embed_k(const int* __restrict__ types,
                        const float* __restrict__ emb) {
    int q = blockIdx.x * 256 + threadIdx.x;   // < 262144
    int node = q >> 4;
    int j = q & 15;
    int t = types[node];
    float4 v = *(const float4*)(emb + t * 64 + j * 4);
    *(float4*)(g_X0 + node * 64 + j * 4) = v;
}

// ---------------------------------------------------------------------------
// Projections: Y1 = x@cw1, Y2 = x@cw2, S1 = x@fw1, S2 = x@fw2
// grid 256 blocks, 64 rows each, 256 threads, 4x8 micro-tiles, FFMA2
// dyn smem: xs[64*68] + ws[64*130]
// ---------------------------------------------------------------------------
#define PROJ_SMEM ((64 * 68 + 64 * 130) * 4)

__global__ void __launch_bounds__(256) proj_k(int flip,
                                              const float* __restrict__ cw12,
                                              const float* __restrict__ fw12) {
    extern __shared__ float sm[];
    float* xs = sm;              // 64 x 68 (padded)
    float* ws = sm + 64 * 68;    // 64 x 130 : [cw1 | cw2 | fw1 | fw2]
    const float* Xc = flip ? g_X1 : g_X0;

    int tid = threadIdx.x;
    int row0 = blockIdx.x * 64;

    for (int t = tid; t < 1024; t += 256) {
        int r = t >> 4, q = t & 15;
        float4 v = *(const float4*)(Xc + (row0 + r) * 64 + q * 4);
        *(float4*)(xs + r * 68 + q * 4) = v;
    }
    for (int t = tid; t < 64 * 128; t += 256) {
        int k = t >> 7, c = t & 127;
        ws[k * 130 + c] = cw12[(c < 64 ? k : 64 + k) * 64 + (c & 63)];
    }
    if (tid < 64) {
        ws[tid * 130 + 128] = fw12[tid];
        ws[tid * 130 + 129] = fw12[64 + tid];
    }
    __syncthreads();

    int rg = tid & 15, cg = tid >> 4;   // 16 row-groups x 16 col-groups
    unsigned long long acc[4][4];
#pragma unroll
    for (int i = 0; i < 4; i++)
#pragma unroll
        for (int p = 0; p < 4; p++) acc[i][p] = 0ull;

#pragma unroll 1
    for (int k = 0; k < 64; k += 4) {
        float4 a[4];
#pragma unroll
        for (int i = 0; i < 4; i++)
            a[i] = *(const float4*)(xs + (rg + 16 * i) * 68 + k);
#pragma unroll
        for (int j = 0; j < 4; j++) {
            unsigned long long bv[4];
#pragma unroll
            for (int p = 0; p < 4; p++)
                bv[p] = *(const unsigned long long*)(ws + (k + j) * 130 +
                                                     cg * 8 + 2 * p);
#pragma unroll
            for (int i = 0; i < 4; i++) {
                float av = ((const float*)(a + i))[j];
                unsigned long long aa = pk2(av, av);
#pragma unroll
                for (int p = 0; p < 4; p++) fma2(acc[i][p], aa, bv[p]);
            }
        }
    }

#pragma unroll
    for (int i = 0; i < 4; i++) {
        int grow = row0 + rg + 16 * i;
#pragma unroll
        for (int p = 0; p < 4; p++) {
            int c = cg * 8 + 2 * p;
            float2 v = up2(acc[i][p]);
            if (c < 64)
                *(float2*)(g_Y1 + grow * 64 + c) = v;
            else
                *(float2*)(g_Y2 + grow * 64 + (c - 64)) = v;
        }
    }

    if (tid < 64) {
        int grow = row0 + tid;
        float s1 = 0.f, s2 = 0.f;
        for (int k = 0; k < 64; k++) {
            float xv = xs[tid * 68 + k];
            s1 += xv * ws[k * 130 + 128];
            s2 += xv * ws[k * 130 + 129];
        }
        g_S1[grow] = s1;
        g_S2[grow] = s2;
    }
}

// ---------------------------------------------------------------------------
// Main conv: one block = 16 atoms (192 (n,m) rows).
//   GEMM: C[192][64] = bond[192][128] @ cw3[128][64]   (FFMA2, 6x8 tiles)
//   Epilogue: +y1 +y2[nbr] +cb, BN, relu, softmax(filt) over m, weighted
//             mean, BN, residual relu -> X_next
// grid 1024, 256 threads, dyn smem ~134KB (1 block/SM)
// ---------------------------------------------------------------------------
#define CONV_SMEM ((25344 + 8448 + 128 + 192) * 4 + 192 * 4)

__global__ void __launch_bounds__(256, 1)
conv_k(int flip, const float* __restrict__ bond, const int* __restrict__ nbrl,
       const float* __restrict__ cw3, const float* __restrict__ fw3,
       const float* __restrict__ cb, const float* __restrict__ fb,
       const float* __restrict__ bag, const float* __restrict__ bab,
       const float* __restrict__ bbg, const float* __restrict__ bbb) {
    extern __shared__ float sm[];
    float* bs = sm;                    // 192 x 132 (padded) bond tile
    float* ws = sm + 25344;            // 128 x 66 weights (k-major, c contig)
    float* fs = ws + 8448;             // 128 filter weights
    float* ft = fs + 128;              // 192 filter values / softmax weights
    int* nb = (int*)(ft + 192);        // 192 neighbor ids

    const float* Xc = flip ? g_X1 : g_X0;
    float* Xn = flip ? g_X0 : g_X1;

    int tid = threadIdx.x;
    int b = blockIdx.x >> 6;
    int n0 = (blockIdx.x & 63) << 4;
    int bn0 = b * 1024 + n0;
    const float* gb = bond + (size_t)bn0 * 12 * 128;

    unsigned bs_s = (unsigned)__cvta_generic_to_shared(bs);
    // two-stage async load of the 96KB bond tile (k halves)
    for (int h = 0; h < 2; h++) {
        for (int t = tid; t < 3072; t += 256) {
            int r = t >> 4, q = t & 15;
            int k = h * 64 + q * 4;
            cp16(bs_s + (r * 132 + k) * 4, gb + r * 128 + k);
        }
        asm volatile("cp.async.commit_group;");
    }
    // weights (small, regular loads)
    for (int t = tid; t < 8192; t += 256) {
        int k = t >> 6, c = t & 63;
        ws[k * 66 + c] = cw3[k * 64 + c];
    }
    if (tid < 128) fs[tid] = fw3[tid];

    int lane = tid & 31, w = tid >> 5;
    int wc = w * 8;   // warp = column group -> B loads broadcast
    unsigned long long acc[6][4];
#pragma unroll
    for (int i = 0; i < 6; i++)
#pragma unroll
        for (int p = 0; p < 4; p++) acc[i][p] = 0ull;

    for (int half = 0; half < 2; half++) {
        if (half == 0)
            asm volatile("cp.async.wait_group 1;");
        else
            asm volatile("cp.async.wait_group 0;");
        __syncthreads();
        int kb = half * 64;
#pragma unroll 1
        for (int kk = 0; kk < 64; kk += 4) {
            int k0 = kb + kk;
            float4 a[6];
#pragma unroll
            for (int i = 0; i < 6; i++)
                a[i] = *(const float4*)(bs + (lane + 32 * i) * 132 + k0);
#pragma unroll
            for (int j = 0; j < 4; j++) {
                unsigned long long bv[4];
#pragma unroll
                for (int p = 0; p < 4; p++)
                    bv[p] = *(const unsigned long long*)(ws + (k0 + j) * 66 +
                                                         wc + 2 * p);
#pragma unroll
                for (int i = 0; i < 6; i++) {
                    float av = ((const float*)(a + i))[j];
                    unsigned long long aa = pk2(av, av);
#pragma unroll
                    for (int p = 0; p < 4; p++) fma2(acc[i][p], aa, bv[p]);
                }
            }
        }
    }

    // filter logits (needs bond tile still in smem)
    float fbv = fb[0];
    if (tid < 192) {
        int row = tid;
        int a_ = row / 12, m = row - a_ * 12;
        int nglob = bn0 + a_;
        int nbr = nbrl[nglob * 12 + m];
        nb[row] = nbr;
        float acc2 = 0.f;
#pragma unroll 8
        for (int k = 0; k < 128; k += 4) {
            float4 bvv = *(const float4*)(bs + row * 132 + k);
            float4 fv = *(const float4*)(fs + k);
            acc2 += bvv.x * fv.x + bvv.y * fv.y + bvv.z * fv.z + bvv.w * fv.w;
        }
        ft[row] = acc2 + g_S1[nglob] + g_S2[b * 1024 + nbr] + fbv;
    }
    __syncthreads();

    // softmax over m (folding the 1/12 mean), done by 16 threads
    if (tid < 16) {
        int base = tid * 12;
        float mx = -1e30f;
#pragma unroll
        for (int m = 0; m < 12; m++) mx = fmaxf(mx, ft[base + m]);
        float s = 0.f;
#pragma unroll
        for (int m = 0; m < 12; m++) s += expf(ft[base + m] - mx);
        float inv = 1.f / (12.f * s);
#pragma unroll
        for (int m = 0; m < 12; m++) ft[base + m] = expf(ft[base + m] - mx) * inv;
    }

    // core epilogue: C + y1 + y2[nbr] + cb -> BN -> relu -> Cs (reuses bs)
    float* Cs = bs;   // 192 x 65
#pragma unroll
    for (int i = 0; i < 6; i++) {
        int row = lane + 32 * i;
        int a_ = row / 12;
        int nglob = bn0 + a_;
        int nbr = nb[row];
        const float* y1p = g_Y1 + nglob * 64 + wc;
        const float* y2p = g_Y2 + (b * 1024 + nbr) * 64 + wc;
#pragma unroll
        for (int p = 0; p < 4; p++) {
            int c = wc + 2 * p;
            float2 v = up2(acc[i][p]);
            float v0 = v.x + y1p[2 * p] + y2p[2 * p] + __ldg(cb + c);
            float v1 = v.y + y1p[2 * p + 1] + y2p[2 * p + 1] + __ldg(cb + c + 1);
            v0 = fmaxf(__ldg(bag + c) * (v0 * BN_ALPHA) + __ldg(bab + c), 0.f);
            v1 = fmaxf(__ldg(bag + c + 1) * (v1 * BN_ALPHA) + __ldg(bab + c + 1),
                       0.f);
            Cs[row * 65 + c] = v0;
            Cs[row * 65 + c + 1] = v1;
        }
    }
    __syncthreads();

    // weighted mean over m, BN, residual relu
#pragma unroll
    for (int q = 0; q < 4; q++) {
        int idx = tid + 256 * q;   // < 1024
        int a_ = idx >> 6, c = idx & 63;
        float s = 0.f;
#pragma unroll
        for (int m = 0; m < 12; m++)
            s += ft[a_ * 12 + m] * Cs[(a_ * 12 + m) * 65 + c];
        s = __ldg(bbg + c) * (s * BN_ALPHA) + __ldg(bbb + c);
        int gi = (bn0 + a_) * 64 + c;
        Xn[gi] = fmaxf(Xc[gi] + s, 0.f);
    }
}

// ---------------------------------------------------------------------------
// Final: crys = relu(gather(x, target_index)); out = relu(crys@dense_w + db)
// grid 16 (per batch), 256 threads
// ---------------------------------------------------------------------------
__global__ void __launch_bounds__(256) final_k(const int* __restrict__ tix,
                                               const float* __restrict__ dw,
                                               const float* __restrict__ db,
                                               float* __restrict__ out) {
    __shared__ float cs[64 * 68];
    __shared__ float wd[64 * 65];
    int b = blockIdx.x, tid = threadIdx.x;
    for (int t = tid; t < 4096; t += 256) {
        int k = t >> 6, f = t & 63;
        wd[k * 65 + f] = dw[t];
    }
    for (int t = tid; t < 1024; t += 256) {
        int j = t >> 4, q = t & 15;
        int ti = tix[b * 64 + j];
        float4 v = *(const float4*)(g_X1 + (b * 1024 + ti) * 64 + q * 4);
        v.x = fmaxf(v.x, 0.f);
        v.y = fmaxf(v.y, 0.f);
        v.z = fmaxf(v.z, 0.f);
        v.w = fmaxf(v.w, 0.f);
        *(float4*)(cs + j * 68 + q * 4) = v;
    }
    __syncthreads();
    for (int t = tid; t < 4096; t += 256) {
        int j = t >> 6, f = t & 63;
        float acc = db[f];
#pragma unroll 8
        for (int k = 0; k < 64; k++) acc += cs[j * 68 + k] * wd[k * 65 + f];
        out[b * 4096 + t] = fmaxf(acc, 0.f);
    }
}

// ---------------------------------------------------------------------------
extern "C" void kernel_launch(void* const* d_in, const int* in_sizes, int n_in,
                              void* d_out, int out_size) {
    const int* atom_types = (const int*)d_in[0];
    const float* bond = (const float*)d_in[1];
    const int* nbrl = (const int*)d_in[2];
    const int* tix = (const int*)d_in[3];
    const float* emb = (const float*)d_in[4];
    const float* core_w = (const float*)d_in[5];
    const float* core_b = (const float*)d_in[6];
    const float* filt_w = (const float*)d_in[7];
    const float* filt_b = (const float*)d_in[8];
    const float* bna_g = (const float*)d_in[9];
    const float* bna_b = (const float*)d_in[10];
    const float* bnb_g = (const float*)d_in[11];
    const float* bnb_b = (const float*)d_in[12];
    const float* dw = (const float*)d_in[13];
    const float* db = (const float*)d_in[14];
    float* out = (float*)d_out;

    cudaFuncSetAttribute(proj_k, cudaFuncAttributeMaxDynamicSharedMemorySize,
                         PROJ_SMEM);
    cudaFuncSetAttribute(conv_k, cudaFuncAttributeMaxDynamicSharedMemorySize,
                         CONV_SMEM);

    embed_k<<<1024, 256>>>(atom_types, emb);
    for (int l = 0; l < 3; l++) {
        int flip = l & 1;
        proj_k<<<256, 256, PROJ_SMEM>>>(flip, core_w + l * 256 * 64,
                                        filt_w + l * 256);
        conv_k<<<1024, 256, CONV_SMEM>>>(
            flip, bond, nbrl, core_w + l * 256 * 64 + 128 * 64,
            filt_w + l * 256 + 128, core_b + l * 64, filt_b + l,
            bna_g + l * 64, bna_b + l * 64, bnb_g + l * 64, bnb_b + l * 64);
    }
    final_k<<<16, 256>>>(tix, dw, db, out);
}